// round 13
// baseline (speedup 1.0000x reference)
#include <cuda_runtime.h>
#include <cuda_bf16.h>
#include <math.h>

#define N_NODES_MAX 100000
#define E_MAX       1600000
#define HID 32
#define IN_DIM 4
#define N_GRAPHS_MAX 64
#define EPSV 1e-5f

#define SCAN_BS 256
#define SCAN_BLOCKS ((N_NODES_MAX + SCAN_BS - 1) / SCAN_BS)   // 391
#define NPAD (SCAN_BLOCKS * SCAN_BS)                          // 100096
#define EB 256          // edges per tile
#define ETH 128         // threads per edge2 block
#define TILES 4         // tiles per edge2 block
#define BUF_W 36        // padded row width (words)
#define MAX_EBLOCKS ((E_MAX + EB - 1) / EB + 1)
#define POOL_BLOCKS 256

typedef unsigned long long ull;

// ---------------- static device scratch (zero at module load) ----------------
__device__ float g_agg[N_NODES_MAX * HID];
__device__ float g_stats[2 * HID];
__device__ float g_gsum[N_GRAPHS_MAX * HID];
__device__ int   g_gcnt[N_GRAPHS_MAX];
__device__ int   g_done;     // phase-1 (stats) arrival counter
__device__ int   g_done2;    // readout ticket

__device__ int g_cnt[NPAD];
__device__ int g_offs[N_NODES_MAX + 1];
__device__ int g_cursor[NPAD];
__device__ int g_src[E_MAX];          // src ids in dst-sorted order
__device__ int g_bstart[MAX_EBLOCKS];

__device__ int g_scan_flag[SCAN_BLOCKS];
__device__ int g_scan_val[SCAN_BLOCKS];
__device__ int g_scan_inc[SCAN_BLOCKS];

// ---------------- helpers ----------------
__device__ __forceinline__ void atomicMaxFloat(float* addr, float v) {
    int vi = __float_as_int(v);
    if (vi >= 0) atomicMax((int*)addr, vi);
    else         atomicMin((unsigned int*)addr, (unsigned int)vi);
}
__device__ __forceinline__ unsigned f2tf(float f) {
    unsigned u;
    asm("cvt.rna.tf32.f32 %0, %1;" : "=r"(u) : "f"(f));
    return u;
}
__device__ __forceinline__ void mma_tf32(float& d0, float& d1, float& d2, float& d3,
                                         unsigned a0, unsigned a1, unsigned a2, unsigned a3,
                                         unsigned b0, unsigned b1) {
    asm volatile(
        "mma.sync.aligned.m16n8k8.row.col.f32.tf32.tf32.f32 "
        "{%0,%1,%2,%3}, {%4,%5,%6,%7}, {%8,%9}, {%0,%1,%2,%3};"
        : "+f"(d0), "+f"(d1), "+f"(d2), "+f"(d3)
        : "r"(a0), "r"(a1), "r"(a2), "r"(a3), "r"(b0), "r"(b1));
}
__device__ __forceinline__ void ldmatrix_x4(unsigned& r0, unsigned& r1,
                                            unsigned& r2, unsigned& r3, unsigned addr) {
    asm volatile("ldmatrix.sync.aligned.m8n8.x4.shared.b16 {%0,%1,%2,%3}, [%4];"
                 : "=r"(r0), "=r"(r1), "=r"(r2), "=r"(r3) : "r"(addr));
}

// ---------------- kernel 1: dst histogram (int4 reads) ----------------
__global__ void hist_kernel(const int* __restrict__ ei, int E) {
    int i = blockIdx.x * blockDim.x + threadIdx.x;
    if ((E & 3) == 0) {
        const int4* d4 = reinterpret_cast<const int4*>(ei + E);
        int n4 = E >> 2;
        if (i < n4) {
            int4 v = d4[i];
            atomicAdd(&g_cnt[v.x], 1);
            atomicAdd(&g_cnt[v.y], 1);
            atomicAdd(&g_cnt[v.z], 1);
            atomicAdd(&g_cnt[v.w], 1);
        }
    } else {
        for (int e = i; e < E; e += gridDim.x * blockDim.x)
            atomicAdd(&g_cnt[ei[E + e]], 1);
    }
}

// ---------------- kernel 2: single-pass scan, warp-parallel lookback ----------------
__global__ void __launch_bounds__(SCAN_BS) scan_kernel(int n, int E) {
    __shared__ int s[SCAN_BS];
    __shared__ int s_prefix;
    const int t = threadIdx.x, b = blockIdx.x;
    int i = b * SCAN_BS + t;
    int v = (i < n) ? g_cnt[i] : 0;
    s[t] = v;
    if (t == 0) s_prefix = 0;
    __syncthreads();
    #pragma unroll
    for (int off = 1; off < SCAN_BS; off <<= 1) {
        int tv = (t >= off) ? s[t - off] : 0;
        __syncthreads();
        s[t] += tv;
        __syncthreads();
    }
    int total = s[SCAN_BS - 1];

    if (b == 0) {
        if (t == 0) {
            g_scan_inc[0] = total;
            __threadfence();
            g_scan_flag[0] = 2;
        }
    } else if (t < 32) {
        if (t == 0) {
            g_scan_val[b] = total;
            __threadfence();
            g_scan_flag[b] = 1;
        }
        __syncwarp();
        int sum = 0;
        int p = b - 1;
        while (true) {
            int idx2 = p - t;
            int f;
            do {
                f = (idx2 >= 0) ? ((volatile int*)g_scan_flag)[idx2] : 2;
            } while (__any_sync(0xffffffffu, f == 0));
            __threadfence();
            int val = 0;
            if (idx2 >= 0)
                val = (f == 2) ? ((volatile int*)g_scan_inc)[idx2]
                               : ((volatile int*)g_scan_val)[idx2];
            unsigned m2 = __ballot_sync(0xffffffffu, f == 2);
            int firstInc = __ffs(m2) - 1;
            int contrib = (firstInc >= 0 && t > firstInc) ? 0 : val;
            #pragma unroll
            for (int o = 16; o > 0; o >>= 1)
                contrib += __shfl_down_sync(0xffffffffu, contrib, o);
            if (t == 0) sum += contrib;
            if (firstInc >= 0) break;
            p -= 32;
        }
        if (t == 0) {
            g_scan_inc[b] = sum + total;
            __threadfence();
            g_scan_flag[b] = 2;
            s_prefix = sum;
        }
    }
    __syncthreads();
    int excl = s_prefix + s[t] - v;
    if (i < n) { g_offs[i] = excl; g_cursor[i] = excl; }
    if (i == 0) g_offs[n] = E;
}

// ---------------- kernel 3: scatter src (4B) + bstart + straddle-node -inf init --------
__global__ void scatter_kernel(const int* __restrict__ ei, int E, int n_nodes) {
    int e = blockIdx.x * blockDim.x + threadIdx.x;
    if (e < E) {
        int sN = ei[e];
        int d = ei[E + e];
        int pos = atomicAdd(&g_cursor[d], 1);
        g_src[pos] = sN;
    }
    if (threadIdx.x == 0) {
        int target = blockIdx.x * EB;
        int lo = 0, hi = n_nodes;
        while (lo < hi) {
            int mid = (lo + hi + 1) >> 1;
            if (g_offs[mid] <= target) lo = mid; else hi = mid - 1;
        }
        g_bstart[blockIdx.x] = lo;
        if (g_offs[lo] < target) {
            const float ninf = __int_as_float(0xFF800000);
            float* row = g_agg + (size_t)lo * HID;
            #pragma unroll
            for (int c = 0; c < HID; c++) row[c] = ninf;
        }
    }
}

// ---------------- kernel 4 (PROFILED SLOT): multi-tile full-MMA edge MLP + seg max ------
__global__ void __launch_bounds__(ETH) edge2_kernel(
    const float* __restrict__ x,
    const float* __restrict__ W1, const float* __restrict__ b1,
    const float* __restrict__ W2, const float* __restrict__ b2,
    int E, int n_nodes, int eblocks)
{
    __shared__ __align__(16) float sW1[2 * IN_DIM * HID];
    __shared__ __align__(16) float sW2[HID * HID];
    __shared__ __align__(16) float sb1[HID];
    __shared__ __align__(16) float sb2[HID];
    __shared__ __align__(16) float sBuf[EB][BUF_W];
    __shared__ int sDst[EB];

    const int tid = threadIdx.x;
    for (int i = tid; i < 2 * IN_DIM * HID; i += ETH) sW1[i] = W1[i];
    for (int i = tid; i < HID * HID; i += ETH)        sW2[i] = W2[i];
    if (tid < HID) { sb1[tid] = b1[tid]; sb2[tid] = b2[tid]; }
    __syncthreads();

    const int lane = tid & 31;
    const int warp = tid >> 5;
    const int grp = lane >> 2;
    const int tig = lane & 3;

    // hoisted B fragments + biases
    unsigned bf1[4][2];
    #pragma unroll
    for (int nt = 0; nt < 4; nt++) {
        bf1[nt][0] = f2tf(sW1[tig * HID + nt * 8 + grp]);
        bf1[nt][1] = f2tf(sW1[(tig + 4) * HID + nt * 8 + grp]);
    }
    unsigned bf2[4][4][2];
    #pragma unroll
    for (int kt = 0; kt < 4; kt++)
        #pragma unroll
        for (int nt = 0; nt < 4; nt++) {
            bf2[kt][nt][0] = f2tf(sW2[(kt * 8 + tig) * HID + nt * 8 + grp]);
            bf2[kt][nt][1] = f2tf(sW2[(kt * 8 + tig + 4) * HID + nt * 8 + grp]);
        }
    float b1lo[4], b1hi[4], b2lo[4], b2hi[4];
    #pragma unroll
    for (int nt = 0; nt < 4; nt++) {
        b1lo[nt] = sb1[nt * 8 + 2 * tig];
        b1hi[nt] = sb1[nt * 8 + 2 * tig + 1];
        b2lo[nt] = sb2[nt * 8 + 2 * tig];
        b2hi[nt] = sb2[nt * 8 + 2 * tig + 1];
    }

    const int q = lane >> 3;
    const int rr = lane & 7;
    const int rowOff = (q & 1) * 8 + rr;
    const int colq = (q >> 1) * 4;
    const unsigned sbase = (unsigned)__cvta_generic_to_shared(&sBuf[0][0]);
    const int baseRow = warp << 6;

    for (int t = 0; t < TILES; t++) {
        const int tb = blockIdx.x * TILES + t;
        if (tb >= eblocks) break;
        const int e0 = tb * EB;
        const int e1 = min(e0 + EB, E);
        const int eA = e0 + tid;
        const int eB2 = e0 + ETH + tid;
        const int nf = g_bstart[tb];

        // fill sDst by walking node ranges (sDst not in use by prior phases here)
        for (int n = nf + warp; n < n_nodes; n += 4) {
            const int on = g_offs[n];
            if (on >= e1) break;
            const int on1 = g_offs[n + 1];
            const int eb = max(on, e0);
            const int ee = min(on1, e1);
            for (int k = eb + lane; k < ee; k += 32) sDst[k - e0] = n;
        }
        __syncthreads();   // sDst ready AND sBuf free (prev segmax done)

        const int dA = (eA  < E) ? sDst[tid] : 0;
        const int dB = (eB2 < E) ? sDst[tid + ETH] : 0;
        const int sA = (eA  < E) ? g_src[eA]  : 0;
        const int sB = (eB2 < E) ? g_src[eB2] : 0;
        const float4 xiA = __ldg(reinterpret_cast<const float4*>(x + (size_t)dA * IN_DIM));
        const float4 xjA = __ldg(reinterpret_cast<const float4*>(x + (size_t)sA * IN_DIM));
        const float4 xiB = __ldg(reinterpret_cast<const float4*>(x + (size_t)dB * IN_DIM));
        const float4 xjB = __ldg(reinterpret_cast<const float4*>(x + (size_t)sB * IN_DIM));

        // msg rows (tf32) -> sBuf cols 0..7
        {
            uint4 m0 = make_uint4(f2tf(xiA.x), f2tf(xiA.y), f2tf(xiA.z), f2tf(xiA.w));
            uint4 m1 = make_uint4(f2tf(xjA.x - xiA.x), f2tf(xjA.y - xiA.y),
                                  f2tf(xjA.z - xiA.z), f2tf(xjA.w - xiA.w));
            *reinterpret_cast<uint4*>(&sBuf[tid][0]) = m0;
            *reinterpret_cast<uint4*>(&sBuf[tid][4]) = m1;
            uint4 n0 = make_uint4(f2tf(xiB.x), f2tf(xiB.y), f2tf(xiB.z), f2tf(xiB.w));
            uint4 n1 = make_uint4(f2tf(xjB.x - xiB.x), f2tf(xjB.y - xiB.y),
                                  f2tf(xjB.z - xiB.z), f2tf(xjB.w - xiB.w));
            *reinterpret_cast<uint4*>(&sBuf[tid + ETH][0]) = n0;
            *reinterpret_cast<uint4*>(&sBuf[tid + ETH][4]) = n1;
        }
        __syncthreads();

        // per-warp [64 x 8] @ W1 -> relu -> [64 x 32] @ W2 on tensor cores
        #pragma unroll
        for (int m = 0; m < 4; m++) {
            const int rowLd = baseRow + m * 16 + rowOff;
            unsigned a0, a1, a2, a3;
            ldmatrix_x4(a0, a1, a2, a3, sbase + (unsigned)((rowLd * BUF_W + colq) * 4));
            float d1[4][4];
            #pragma unroll
            for (int nt = 0; nt < 4; nt++) {
                d1[nt][0] = b1lo[nt]; d1[nt][1] = b1hi[nt];
                d1[nt][2] = b1lo[nt]; d1[nt][3] = b1hi[nt];
                mma_tf32(d1[nt][0], d1[nt][1], d1[nt][2], d1[nt][3],
                         a0, a1, a2, a3, bf1[nt][0], bf1[nt][1]);
            }
            const int r0 = baseRow + m * 16 + grp;
            #pragma unroll
            for (int nt = 0; nt < 4; nt++) {
                *reinterpret_cast<uint2*>(&sBuf[r0][nt * 8 + 2 * tig]) =
                    make_uint2(f2tf(fmaxf(d1[nt][0], 0.f)), f2tf(fmaxf(d1[nt][1], 0.f)));
                *reinterpret_cast<uint2*>(&sBuf[r0 + 8][nt * 8 + 2 * tig]) =
                    make_uint2(f2tf(fmaxf(d1[nt][2], 0.f)), f2tf(fmaxf(d1[nt][3], 0.f)));
            }
            float d2[4][4];
            #pragma unroll
            for (int nt = 0; nt < 4; nt++) {
                d2[nt][0] = b2lo[nt]; d2[nt][1] = b2hi[nt];
                d2[nt][2] = b2lo[nt]; d2[nt][3] = b2hi[nt];
            }
            #pragma unroll
            for (int kt = 0; kt < 4; kt++) {
                unsigned h0, h1, h2, h3;
                ldmatrix_x4(h0, h1, h2, h3,
                            sbase + (unsigned)((rowLd * BUF_W + kt * 8 + colq) * 4));
                #pragma unroll
                for (int nt = 0; nt < 4; nt++)
                    mma_tf32(d2[nt][0], d2[nt][1], d2[nt][2], d2[nt][3],
                             h0, h1, h2, h3, bf2[kt][nt][0], bf2[kt][nt][1]);
            }
            #pragma unroll
            for (int nt = 0; nt < 4; nt++) {
                *reinterpret_cast<float2*>(&sBuf[r0][nt * 8 + 2 * tig]) =
                    make_float2(d2[nt][0], d2[nt][1]);
                *reinterpret_cast<float2*>(&sBuf[r0 + 8][nt * 8 + 2 * tig]) =
                    make_float2(d2[nt][2], d2[nt][3]);
            }
        }
        __syncthreads();

        // segmented max over this tile's edge range
        for (int n = nf + warp; n < n_nodes; n += 4) {
            const int on = g_offs[n];
            if (on >= e1) break;
            const int on1 = g_offs[n + 1];
            const int eb = max(on, e0);
            const int ee = min(on1, e1);
            float m = -INFINITY;
            for (int k = eb; k < ee; k++) m = fmaxf(m, sBuf[k - e0][lane]);
            const bool interior = (on >= e0) && (on1 <= e1);
            if (interior) {
                g_agg[(size_t)n * HID + lane] = m;
            } else if (eb < ee) {
                atomicMaxFloat(&g_agg[(size_t)n * HID + lane], m);
            }
        }
    }
}

// ---------------- kernel 5: fused stats + BN + pool + readout (grid-sync) ----------------
__global__ void __launch_bounds__(256) pool_final_kernel(
    const int* __restrict__ batch, int n_nodes,
    const float* __restrict__ gamma, const float* __restrict__ beta,
    const float* __restrict__ Wr1, const float* __restrict__ br1,
    const float* __restrict__ Wr2, const float* __restrict__ br2,
    float* __restrict__ out, int n_graphs)
{
    const int t = threadIdx.x;
    const int gtid = blockIdx.x * blockDim.x + t;
    const int gstride = gridDim.x * blockDim.x;

    // phase 0: deferred zeroing for next replay (g_cnt consumed by scan already)
    for (int i = gtid; i < NPAD; i += gstride) g_cnt[i] = 0;
    if (gtid < SCAN_BLOCKS) g_scan_flag[gtid] = 0;

    // phase 1: BN stats over g_agg (sanitize -inf on read)
    {
        float4 sum = make_float4(0.f, 0.f, 0.f, 0.f);
        float4 sq  = make_float4(0.f, 0.f, 0.f, 0.f);
        int tot4 = n_nodes * HID / 4;
        const float4* agg4 = reinterpret_cast<const float4*>(g_agg);
        for (int i = gtid; i < tot4; i += gstride) {
            float4 v = agg4[i];
            if (!isfinite(v.x)) v.x = 0.f;
            if (!isfinite(v.y)) v.y = 0.f;
            if (!isfinite(v.z)) v.z = 0.f;
            if (!isfinite(v.w)) v.w = 0.f;
            sum.x += v.x; sum.y += v.y; sum.z += v.z; sum.w += v.w;
            sq.x += v.x * v.x; sq.y += v.y * v.y; sq.z += v.z * v.z; sq.w += v.w * v.w;
        }
        __shared__ float4 sS[256], sQ[256];
        sS[t] = sum; sQ[t] = sq;
        __syncthreads();
        #pragma unroll
        for (int s = 128; s >= 8; s >>= 1) {
            if (t < s) {
                float4 a = sS[t], b = sS[t + s];
                sS[t] = make_float4(a.x + b.x, a.y + b.y, a.z + b.z, a.w + b.w);
                float4 cq = sQ[t], d = sQ[t + s];
                sQ[t] = make_float4(cq.x + d.x, cq.y + d.y, cq.z + d.z, cq.w + d.w);
            }
            __syncthreads();
        }
        if (t < 8) {
            int cb = 4 * t;
            float4 a = sS[t], cq = sQ[t];
            atomicAdd(&g_stats[cb + 0], a.x); atomicAdd(&g_stats[cb + 1], a.y);
            atomicAdd(&g_stats[cb + 2], a.z); atomicAdd(&g_stats[cb + 3], a.w);
            atomicAdd(&g_stats[HID + cb + 0], cq.x); atomicAdd(&g_stats[HID + cb + 1], cq.y);
            atomicAdd(&g_stats[HID + cb + 2], cq.z); atomicAdd(&g_stats[HID + cb + 3], cq.w);
            __threadfence();
        }
        __syncthreads();
    }

    // grid barrier: all blocks' stats visible before BN fold
    if (t == 0) {
        atomicAdd(&g_done, 1);
        while (((volatile int*)&g_done)[0] < gridDim.x) { }
    }
    __syncthreads();
    __threadfence();

    // phase 2: BN fold + pool
    const int c = t & 31;
    const int w = t >> 5;
    float inv_n = 1.f / (float)n_nodes;
    float mean = g_stats[c] * inv_n;
    float var = g_stats[HID + c] * inv_n - mean * mean;
    float sc = gamma[c] * rsqrtf(var + EPSV);
    float sh = beta[c] - mean * sc;

    int chunk = (n_nodes + gridDim.x - 1) / gridDim.x;
    int n0 = blockIdx.x * chunk;
    int n1 = min(n0 + chunk, n_nodes);

    float acc = 0.f;
    int cur = -1;
    int cnt = 0;
    for (int n = n0 + w; n < n1; n += 8) {
        int g = batch[n];
        float v = g_agg[(size_t)n * HID + c];
        if (!isfinite(v)) v = 0.f;
        v = fmaxf(v * sc + sh, 0.f);
        if (g != cur) {
            if (cur >= 0) {
                atomicAdd(&g_gsum[cur * HID + c], acc);
                if (c == 0) atomicAdd(&g_gcnt[cur], cnt);
            }
            cur = g; acc = 0.f; cnt = 0;
        }
        acc += v; cnt++;
    }
    if (cur >= 0) {
        atomicAdd(&g_gsum[cur * HID + c], acc);
        if (c == 0) atomicAdd(&g_gcnt[cur], cnt);
    }

    // readout ticket
    __shared__ int s_last;
    __threadfence();
    __syncthreads();
    if (t == 0) {
        int ticket = atomicAdd(&g_done2, 1);
        s_last = (ticket == gridDim.x - 1);
    }
    __syncthreads();
    if (s_last) {
        __threadfence();
        int g = t;
        float o = 0.f;
        bool wr = (g < n_graphs);
        if (wr) {
            float inv_cnt = 1.f / fmaxf((float)g_gcnt[g], 1.f);
            float p[HID];
            #pragma unroll
            for (int k = 0; k < HID; k++) p[k] = g_gsum[g * HID + k] * inv_cnt;
            float h[16];
            #pragma unroll
            for (int m = 0; m < 16; m++) {
                float a = br1[m];
                #pragma unroll
                for (int k = 0; k < HID; k++) a += p[k] * Wr1[k * 16 + m];
                h[m] = fmaxf(a, 0.f);
            }
            o = br2[0];
            #pragma unroll
            for (int m = 0; m < 16; m++) o += h[m] * Wr2[m];
        }
        __syncthreads();
        if (wr) out[g] = o;
        // deferred cleanup for next replay
        for (int i = t; i < N_GRAPHS_MAX * HID; i += blockDim.x) g_gsum[i] = 0.f;
        if (t < N_GRAPHS_MAX) g_gcnt[t] = 0;
        if (t < 2 * HID) g_stats[t] = 0.f;
        if (t == 0) { g_done = 0; g_done2 = 0; }
    }
}

// ---------------- launch ----------------
extern "C" void kernel_launch(void* const* d_in, const int* in_sizes, int n_in,
                              void* d_out, int out_size) {
    const float* x     = (const float*)d_in[0];
    const int*   ei    = (const int*)d_in[1];
    const int*   batch = (const int*)d_in[2];
    const float* W1    = (const float*)d_in[3];
    const float* b1    = (const float*)d_in[4];
    const float* W2    = (const float*)d_in[5];
    const float* b2    = (const float*)d_in[6];
    const float* gamma = (const float*)d_in[7];
    const float* beta  = (const float*)d_in[8];
    const float* Wr1   = (const float*)d_in[9];
    const float* br1   = (const float*)d_in[10];
    const float* Wr2   = (const float*)d_in[11];
    const float* br2   = (const float*)d_in[12];
    float* out = (float*)d_out;

    int E        = in_sizes[1] / 2;
    int n_nodes  = in_sizes[2];
    int n_graphs = out_size;
    int eblocks  = (E + EB - 1) / EB;
    int e2blocks = (eblocks + TILES - 1) / TILES;
    int hblocks  = ((E & 3) == 0) ? ((E / 4) + 255) / 256 : 1184;

    hist_kernel<<<hblocks, 256>>>(ei, E);
    scan_kernel<<<SCAN_BLOCKS, SCAN_BS>>>(n_nodes, E);
    scatter_kernel<<<eblocks, EB>>>(ei, E, n_nodes);
    edge2_kernel<<<e2blocks, ETH>>>(x, W1, b1, W2, b2, E, n_nodes, eblocks);
    pool_final_kernel<<<POOL_BLOCKS, 256>>>(batch, n_nodes, gamma, beta,
                                            Wr1, br1, Wr2, br2, out, n_graphs);
}

// round 14
// speedup vs baseline: 1.0916x; 1.0916x over previous
#include <cuda_runtime.h>
#include <cuda_bf16.h>
#include <math.h>

#define N_NODES_MAX 100000
#define E_MAX       1600000
#define HID 32
#define IN_DIM 4
#define N_GRAPHS_MAX 64
#define EPSV 1e-5f

#define SCAN_BS 256
#define SCAN_BLOCKS ((N_NODES_MAX + SCAN_BS - 1) / SCAN_BS)   // 391
#define NPAD (SCAN_BLOCKS * SCAN_BS)                          // 100096
#define EB 256          // edges per tile
#define ETH 128         // threads per edge2 block
#define TILES 4         // tiles per edge2 block
#define BUF_W 36        // padded row width (words)
#define MAX_EBLOCKS ((E_MAX + EB - 1) / EB + 1)
#define POOL_BLOCKS 256

typedef unsigned long long ull;

// ---------------- static device scratch (zero at module load) ----------------
__device__ float g_agg[N_NODES_MAX * HID];
__device__ float g_stats[2 * HID];
__device__ float g_gsum[N_GRAPHS_MAX * HID];
__device__ int   g_gcnt[N_GRAPHS_MAX];
__device__ int   g_done;     // stats grid-barrier counter
__device__ int   g_done2;    // readout ticket

__device__ int g_cnt[NPAD];
__device__ int g_offs[N_NODES_MAX + 1];
__device__ int g_cursor[NPAD];
__device__ int2 g_esorted[E_MAX];     // (src, dst) sorted by dst
__device__ int g_bstart[MAX_EBLOCKS];

__device__ int g_scan_flag[SCAN_BLOCKS];
__device__ int g_scan_val[SCAN_BLOCKS];
__device__ int g_scan_inc[SCAN_BLOCKS];

// ---------------- helpers ----------------
__device__ __forceinline__ void atomicMaxFloat(float* addr, float v) {
    int vi = __float_as_int(v);
    if (vi >= 0) atomicMax((int*)addr, vi);
    else         atomicMin((unsigned int*)addr, (unsigned int)vi);
}
__device__ __forceinline__ unsigned f2tf(float f) {
    unsigned u;
    asm("cvt.rna.tf32.f32 %0, %1;" : "=r"(u) : "f"(f));
    return u;
}
__device__ __forceinline__ void mma_tf32(float& d0, float& d1, float& d2, float& d3,
                                         unsigned a0, unsigned a1, unsigned a2, unsigned a3,
                                         unsigned b0, unsigned b1) {
    asm volatile(
        "mma.sync.aligned.m16n8k8.row.col.f32.tf32.tf32.f32 "
        "{%0,%1,%2,%3}, {%4,%5,%6,%7}, {%8,%9}, {%0,%1,%2,%3};"
        : "+f"(d0), "+f"(d1), "+f"(d2), "+f"(d3)
        : "r"(a0), "r"(a1), "r"(a2), "r"(a3), "r"(b0), "r"(b1));
}
__device__ __forceinline__ void ldmatrix_x4(unsigned& r0, unsigned& r1,
                                            unsigned& r2, unsigned& r3, unsigned addr) {
    asm volatile("ldmatrix.sync.aligned.m8n8.x4.shared.b16 {%0,%1,%2,%3}, [%4];"
                 : "=r"(r0), "=r"(r1), "=r"(r2), "=r"(r3) : "r"(addr));
}

// ---------------- kernel 1: dst histogram (int4 reads) ----------------
__global__ void hist_kernel(const int* __restrict__ ei, int E) {
    int i = blockIdx.x * blockDim.x + threadIdx.x;
    if ((E & 3) == 0) {
        const int4* d4 = reinterpret_cast<const int4*>(ei + E);
        int n4 = E >> 2;
        if (i < n4) {
            int4 v = d4[i];
            atomicAdd(&g_cnt[v.x], 1);
            atomicAdd(&g_cnt[v.y], 1);
            atomicAdd(&g_cnt[v.z], 1);
            atomicAdd(&g_cnt[v.w], 1);
        }
    } else {
        for (int e = i; e < E; e += gridDim.x * blockDim.x)
            atomicAdd(&g_cnt[ei[E + e]], 1);
    }
}

// ---------------- kernel 2: single-pass scan, warp-parallel lookback ----------------
__global__ void __launch_bounds__(SCAN_BS) scan_kernel(int n, int E) {
    __shared__ int s[SCAN_BS];
    __shared__ int s_prefix;
    const int t = threadIdx.x, b = blockIdx.x;
    int i = b * SCAN_BS + t;
    int v = (i < n) ? g_cnt[i] : 0;
    s[t] = v;
    if (t == 0) s_prefix = 0;
    __syncthreads();
    #pragma unroll
    for (int off = 1; off < SCAN_BS; off <<= 1) {
        int tv = (t >= off) ? s[t - off] : 0;
        __syncthreads();
        s[t] += tv;
        __syncthreads();
    }
    int total = s[SCAN_BS - 1];

    if (b == 0) {
        if (t == 0) {
            g_scan_inc[0] = total;
            __threadfence();
            g_scan_flag[0] = 2;
        }
    } else if (t < 32) {
        if (t == 0) {
            g_scan_val[b] = total;
            __threadfence();
            g_scan_flag[b] = 1;
        }
        __syncwarp();
        int sum = 0;
        int p = b - 1;
        while (true) {
            int idx2 = p - t;
            int f;
            do {
                f = (idx2 >= 0) ? ((volatile int*)g_scan_flag)[idx2] : 2;
            } while (__any_sync(0xffffffffu, f == 0));
            __threadfence();
            int val = 0;
            if (idx2 >= 0)
                val = (f == 2) ? ((volatile int*)g_scan_inc)[idx2]
                               : ((volatile int*)g_scan_val)[idx2];
            unsigned m2 = __ballot_sync(0xffffffffu, f == 2);
            int firstInc = __ffs(m2) - 1;
            int contrib = (firstInc >= 0 && t > firstInc) ? 0 : val;
            #pragma unroll
            for (int o = 16; o > 0; o >>= 1)
                contrib += __shfl_down_sync(0xffffffffu, contrib, o);
            if (t == 0) sum += contrib;
            if (firstInc >= 0) break;
            p -= 32;
        }
        if (t == 0) {
            g_scan_inc[b] = sum + total;
            __threadfence();
            g_scan_flag[b] = 2;
            s_prefix = sum;
        }
    }
    __syncthreads();
    int excl = s_prefix + s[t] - v;
    if (i < n) { g_offs[i] = excl; g_cursor[i] = excl; }
    if (i == 0) g_offs[n] = E;
}

// ---------------- kernel 3: scatter (src,dst) + bstart + straddle-node -inf init --------
__global__ void scatter_kernel(const int* __restrict__ ei, int E, int n_nodes) {
    int e = blockIdx.x * blockDim.x + threadIdx.x;
    if (e < E) {
        int sN = ei[e];
        int d = ei[E + e];
        int pos = atomicAdd(&g_cursor[d], 1);
        g_esorted[pos] = make_int2(sN, d);
    }
    if (threadIdx.x == 0) {
        int target = blockIdx.x * EB;
        int lo = 0, hi = n_nodes;
        while (lo < hi) {
            int mid = (lo + hi + 1) >> 1;
            if (g_offs[mid] <= target) lo = mid; else hi = mid - 1;
        }
        g_bstart[blockIdx.x] = lo;
        if (g_offs[lo] < target) {
            const float ninf = __int_as_float(0xFF800000);
            float* row = g_agg + (size_t)lo * HID;
            #pragma unroll
            for (int c = 0; c < HID; c++) row[c] = ninf;
        }
    }
}

// ---------------- kernel 4 (PROFILED SLOT): multi-tile full-MMA edge MLP + seg max ------
// R12 version verbatim (measured 88 us) — the R13 sDst variant regressed.
__global__ void __launch_bounds__(ETH) edge2_kernel(
    const float* __restrict__ x,
    const float* __restrict__ W1, const float* __restrict__ b1,
    const float* __restrict__ W2, const float* __restrict__ b2,
    int E, int n_nodes, int eblocks)
{
    __shared__ __align__(16) float sW1[2 * IN_DIM * HID];
    __shared__ __align__(16) float sW2[HID * HID];
    __shared__ __align__(16) float sb1[HID];
    __shared__ __align__(16) float sb2[HID];
    __shared__ __align__(16) float sBuf[EB][BUF_W];

    const int tid = threadIdx.x;
    for (int i = tid; i < 2 * IN_DIM * HID; i += ETH) sW1[i] = W1[i];
    for (int i = tid; i < HID * HID; i += ETH)        sW2[i] = W2[i];
    if (tid < HID) { sb1[tid] = b1[tid]; sb2[tid] = b2[tid]; }
    __syncthreads();

    const int lane = tid & 31;
    const int warp = tid >> 5;
    const int grp = lane >> 2;
    const int tig = lane & 3;

    // hoisted B fragments + biases
    unsigned bf1[4][2];
    #pragma unroll
    for (int nt = 0; nt < 4; nt++) {
        bf1[nt][0] = f2tf(sW1[tig * HID + nt * 8 + grp]);
        bf1[nt][1] = f2tf(sW1[(tig + 4) * HID + nt * 8 + grp]);
    }
    unsigned bf2[4][4][2];
    #pragma unroll
    for (int kt = 0; kt < 4; kt++)
        #pragma unroll
        for (int nt = 0; nt < 4; nt++) {
            bf2[kt][nt][0] = f2tf(sW2[(kt * 8 + tig) * HID + nt * 8 + grp]);
            bf2[kt][nt][1] = f2tf(sW2[(kt * 8 + tig + 4) * HID + nt * 8 + grp]);
        }
    float b1lo[4], b1hi[4], b2lo[4], b2hi[4];
    #pragma unroll
    for (int nt = 0; nt < 4; nt++) {
        b1lo[nt] = sb1[nt * 8 + 2 * tig];
        b1hi[nt] = sb1[nt * 8 + 2 * tig + 1];
        b2lo[nt] = sb2[nt * 8 + 2 * tig];
        b2hi[nt] = sb2[nt * 8 + 2 * tig + 1];
    }

    const int q = lane >> 3;
    const int rr = lane & 7;
    const int rowOff = (q & 1) * 8 + rr;
    const int colq = (q >> 1) * 4;
    const unsigned sbase = (unsigned)__cvta_generic_to_shared(&sBuf[0][0]);
    const int baseRow = warp << 6;

    for (int t = 0; t < TILES; t++) {
        const int tb = blockIdx.x * TILES + t;
        if (tb >= eblocks) break;
        const int e0 = tb * EB;
        const int e1 = min(e0 + EB, E);
        const int eA = e0 + tid;
        const int eB2 = e0 + ETH + tid;

        __syncthreads();          // sBuf free (prev tile's segmax done)

        const int2 sdA = (eA  < E) ? g_esorted[eA]  : make_int2(0, 0);
        const int2 sdB = (eB2 < E) ? g_esorted[eB2] : make_int2(0, 0);
        const float4 xiA = __ldg(reinterpret_cast<const float4*>(x + (size_t)sdA.y * IN_DIM));
        const float4 xjA = __ldg(reinterpret_cast<const float4*>(x + (size_t)sdA.x * IN_DIM));
        const float4 xiB = __ldg(reinterpret_cast<const float4*>(x + (size_t)sdB.y * IN_DIM));
        const float4 xjB = __ldg(reinterpret_cast<const float4*>(x + (size_t)sdB.x * IN_DIM));

        // msg rows (tf32) -> sBuf cols 0..7
        {
            uint4 m0 = make_uint4(f2tf(xiA.x), f2tf(xiA.y), f2tf(xiA.z), f2tf(xiA.w));
            uint4 m1 = make_uint4(f2tf(xjA.x - xiA.x), f2tf(xjA.y - xiA.y),
                                  f2tf(xjA.z - xiA.z), f2tf(xjA.w - xiA.w));
            *reinterpret_cast<uint4*>(&sBuf[tid][0]) = m0;
            *reinterpret_cast<uint4*>(&sBuf[tid][4]) = m1;
            uint4 n0 = make_uint4(f2tf(xiB.x), f2tf(xiB.y), f2tf(xiB.z), f2tf(xiB.w));
            uint4 n1 = make_uint4(f2tf(xjB.x - xiB.x), f2tf(xjB.y - xiB.y),
                                  f2tf(xjB.z - xiB.z), f2tf(xjB.w - xiB.w));
            *reinterpret_cast<uint4*>(&sBuf[tid + ETH][0]) = n0;
            *reinterpret_cast<uint4*>(&sBuf[tid + ETH][4]) = n1;
        }
        __syncthreads();

        // per-warp [64 x 8] @ W1 -> relu -> [64 x 32] @ W2 on tensor cores
        #pragma unroll
        for (int m = 0; m < 4; m++) {
            const int rowLd = baseRow + m * 16 + rowOff;
            unsigned a0, a1, a2, a3;
            ldmatrix_x4(a0, a1, a2, a3, sbase + (unsigned)((rowLd * BUF_W + colq) * 4));
            float d1[4][4];
            #pragma unroll
            for (int nt = 0; nt < 4; nt++) {
                d1[nt][0] = b1lo[nt]; d1[nt][1] = b1hi[nt];
                d1[nt][2] = b1lo[nt]; d1[nt][3] = b1hi[nt];
                mma_tf32(d1[nt][0], d1[nt][1], d1[nt][2], d1[nt][3],
                         a0, a1, a2, a3, bf1[nt][0], bf1[nt][1]);
            }
            const int r0 = baseRow + m * 16 + grp;
            #pragma unroll
            for (int nt = 0; nt < 4; nt++) {
                *reinterpret_cast<uint2*>(&sBuf[r0][nt * 8 + 2 * tig]) =
                    make_uint2(f2tf(fmaxf(d1[nt][0], 0.f)), f2tf(fmaxf(d1[nt][1], 0.f)));
                *reinterpret_cast<uint2*>(&sBuf[r0 + 8][nt * 8 + 2 * tig]) =
                    make_uint2(f2tf(fmaxf(d1[nt][2], 0.f)), f2tf(fmaxf(d1[nt][3], 0.f)));
            }
            float d2[4][4];
            #pragma unroll
            for (int nt = 0; nt < 4; nt++) {
                d2[nt][0] = b2lo[nt]; d2[nt][1] = b2hi[nt];
                d2[nt][2] = b2lo[nt]; d2[nt][3] = b2hi[nt];
            }
            #pragma unroll
            for (int kt = 0; kt < 4; kt++) {
                unsigned h0, h1, h2, h3;
                ldmatrix_x4(h0, h1, h2, h3,
                            sbase + (unsigned)((rowLd * BUF_W + kt * 8 + colq) * 4));
                #pragma unroll
                for (int nt = 0; nt < 4; nt++)
                    mma_tf32(d2[nt][0], d2[nt][1], d2[nt][2], d2[nt][3],
                             h0, h1, h2, h3, bf2[kt][nt][0], bf2[kt][nt][1]);
            }
            #pragma unroll
            for (int nt = 0; nt < 4; nt++) {
                *reinterpret_cast<float2*>(&sBuf[r0][nt * 8 + 2 * tig]) =
                    make_float2(d2[nt][0], d2[nt][1]);
                *reinterpret_cast<float2*>(&sBuf[r0 + 8][nt * 8 + 2 * tig]) =
                    make_float2(d2[nt][2], d2[nt][3]);
            }
        }
        __syncthreads();

        // segmented max over this tile's edge range (4 warps, stride 4 over nodes)
        const int nf = g_bstart[tb];
        for (int n = nf + warp; n < n_nodes; n += 4) {
            const int on = g_offs[n];
            if (on >= e1) break;
            const int on1 = g_offs[n + 1];
            const int eb = max(on, e0);
            const int ee = min(on1, e1);
            float m = -INFINITY;
            for (int k = eb; k < ee; k++) m = fmaxf(m, sBuf[k - e0][lane]);
            const bool interior = (on >= e0) && (on1 <= e1);
            if (interior) {
                g_agg[(size_t)n * HID + lane] = m;
            } else if (eb < ee) {
                atomicMaxFloat(&g_agg[(size_t)n * HID + lane], m);
            }
        }
    }
}

// ---------------- kernel 5: fused stats + BN + pool + readout (grid-sync) ----------------
__global__ void __launch_bounds__(256) pool_final_kernel(
    const int* __restrict__ batch, int n_nodes,
    const float* __restrict__ gamma, const float* __restrict__ beta,
    const float* __restrict__ Wr1, const float* __restrict__ br1,
    const float* __restrict__ Wr2, const float* __restrict__ br2,
    float* __restrict__ out, int n_graphs)
{
    const int t = threadIdx.x;
    const int gtid = blockIdx.x * blockDim.x + t;
    const int gstride = gridDim.x * blockDim.x;

    // phase 0: deferred zeroing for next replay
    for (int i = gtid; i < NPAD; i += gstride) g_cnt[i] = 0;
    if (gtid < SCAN_BLOCKS) g_scan_flag[gtid] = 0;

    // phase 1: BN stats over g_agg (sanitize -inf on read)
    {
        float4 sum = make_float4(0.f, 0.f, 0.f, 0.f);
        float4 sq  = make_float4(0.f, 0.f, 0.f, 0.f);
        int tot4 = n_nodes * HID / 4;
        const float4* agg4 = reinterpret_cast<const float4*>(g_agg);
        for (int i = gtid; i < tot4; i += gstride) {
            float4 v = agg4[i];
            if (!isfinite(v.x)) v.x = 0.f;
            if (!isfinite(v.y)) v.y = 0.f;
            if (!isfinite(v.z)) v.z = 0.f;
            if (!isfinite(v.w)) v.w = 0.f;
            sum.x += v.x; sum.y += v.y; sum.z += v.z; sum.w += v.w;
            sq.x += v.x * v.x; sq.y += v.y * v.y; sq.z += v.z * v.z; sq.w += v.w * v.w;
        }
        __shared__ float4 sS[256], sQ[256];
        sS[t] = sum; sQ[t] = sq;
        __syncthreads();
        #pragma unroll
        for (int s = 128; s >= 8; s >>= 1) {
            if (t < s) {
                float4 a = sS[t], b = sS[t + s];
                sS[t] = make_float4(a.x + b.x, a.y + b.y, a.z + b.z, a.w + b.w);
                float4 cq = sQ[t], d = sQ[t + s];
                sQ[t] = make_float4(cq.x + d.x, cq.y + d.y, cq.z + d.z, cq.w + d.w);
            }
            __syncthreads();
        }
        if (t < 8) {
            int cb = 4 * t;
            float4 a = sS[t], cq = sQ[t];
            atomicAdd(&g_stats[cb + 0], a.x); atomicAdd(&g_stats[cb + 1], a.y);
            atomicAdd(&g_stats[cb + 2], a.z); atomicAdd(&g_stats[cb + 3], a.w);
            atomicAdd(&g_stats[HID + cb + 0], cq.x); atomicAdd(&g_stats[HID + cb + 1], cq.y);
            atomicAdd(&g_stats[HID + cb + 2], cq.z); atomicAdd(&g_stats[HID + cb + 3], cq.w);
            __threadfence();
        }
        __syncthreads();
    }

    // grid barrier: all blocks' stats visible before BN fold
    if (t == 0) {
        atomicAdd(&g_done, 1);
        while (((volatile int*)&g_done)[0] < gridDim.x) { }
    }
    __syncthreads();
    __threadfence();

    // phase 2: BN fold + pool
    const int c = t & 31;
    const int w = t >> 5;
    float inv_n = 1.f / (float)n_nodes;
    float mean = g_stats[c] * inv_n;
    float var = g_stats[HID + c] * inv_n - mean * mean;
    float sc = gamma[c] * rsqrtf(var + EPSV);
    float sh = beta[c] - mean * sc;

    int chunk = (n_nodes + gridDim.x - 1) / gridDim.x;
    int n0 = blockIdx.x * chunk;
    int n1 = min(n0 + chunk, n_nodes);

    float acc = 0.f;
    int cur = -1;
    int cnt = 0;
    for (int n = n0 + w; n < n1; n += 8) {
        int g = batch[n];
        float v = g_agg[(size_t)n * HID + c];
        if (!isfinite(v)) v = 0.f;
        v = fmaxf(v * sc + sh, 0.f);
        if (g != cur) {
            if (cur >= 0) {
                atomicAdd(&g_gsum[cur * HID + c], acc);
                if (c == 0) atomicAdd(&g_gcnt[cur], cnt);
            }
            cur = g; acc = 0.f; cnt = 0;
        }
        acc += v; cnt++;
    }
    if (cur >= 0) {
        atomicAdd(&g_gsum[cur * HID + c], acc);
        if (c == 0) atomicAdd(&g_gcnt[cur], cnt);
    }

    // readout ticket
    __shared__ int s_last;
    __threadfence();
    __syncthreads();
    if (t == 0) {
        int ticket = atomicAdd(&g_done2, 1);
        s_last = (ticket == gridDim.x - 1);
    }
    __syncthreads();
    if (s_last) {
        __threadfence();
        int g = t;
        float o = 0.f;
        bool wr = (g < n_graphs);
        if (wr) {
            float inv_cnt = 1.f / fmaxf((float)g_gcnt[g], 1.f);
            float p[HID];
            #pragma unroll
            for (int k = 0; k < HID; k++) p[k] = g_gsum[g * HID + k] * inv_cnt;
            float h[16];
            #pragma unroll
            for (int m = 0; m < 16; m++) {
                float a = br1[m];
                #pragma unroll
                for (int k = 0; k < HID; k++) a += p[k] * Wr1[k * 16 + m];
                h[m] = fmaxf(a, 0.f);
            }
            o = br2[0];
            #pragma unroll
            for (int m = 0; m < 16; m++) o += h[m] * Wr2[m];
        }
        __syncthreads();
        if (wr) out[g] = o;
        // deferred cleanup for next replay
        for (int i = t; i < N_GRAPHS_MAX * HID; i += blockDim.x) g_gsum[i] = 0.f;
        if (t < N_GRAPHS_MAX) g_gcnt[t] = 0;
        if (t < 2 * HID) g_stats[t] = 0.f;
        if (t == 0) { g_done = 0; g_done2 = 0; }
    }
}

// ---------------- launch ----------------
extern "C" void kernel_launch(void* const* d_in, const int* in_sizes, int n_in,
                              void* d_out, int out_size) {
    const float* x     = (const float*)d_in[0];
    const int*   ei    = (const int*)d_in[1];
    const int*   batch = (const int*)d_in[2];
    const float* W1    = (const float*)d_in[3];
    const float* b1    = (const float*)d_in[4];
    const float* W2    = (const float*)d_in[5];
    const float* b2    = (const float*)d_in[6];
    const float* gamma = (const float*)d_in[7];
    const float* beta  = (const float*)d_in[8];
    const float* Wr1   = (const float*)d_in[9];
    const float* br1   = (const float*)d_in[10];
    const float* Wr2   = (const float*)d_in[11];
    const float* br2   = (const float*)d_in[12];
    float* out = (float*)d_out;

    int E        = in_sizes[1] / 2;
    int n_nodes  = in_sizes[2];
    int n_graphs = out_size;
    int eblocks  = (E + EB - 1) / EB;
    int e2blocks = (eblocks + TILES - 1) / TILES;
    int hblocks  = ((E & 3) == 0) ? ((E / 4) + 255) / 256 : 1184;

    hist_kernel<<<hblocks, 256>>>(ei, E);
    scan_kernel<<<SCAN_BLOCKS, SCAN_BS>>>(n_nodes, E);
    scatter_kernel<<<eblocks, EB>>>(ei, E, n_nodes);
    edge2_kernel<<<e2blocks, ETH>>>(x, W1, b1, W2, b2, E, n_nodes, eblocks);
    pool_final_kernel<<<POOL_BLOCKS, 256>>>(batch, n_nodes, gamma, beta,
                                            Wr1, br1, Wr2, br2, out, n_graphs);
}